// round 8
// baseline (speedup 1.0000x reference)
#include <cuda_runtime.h>
#include <cuda_bf16.h>
#include <cstdint>

#define B_I 3072   // 256*12 batched signals
#define N_N 2048   // signal length
#define M_M 512    // measurements
#define NITER 100

typedef unsigned int u32;

// ---------------------------------------------------------------------------
// bf16x3 split GEMM operands, fragment order for mma.m16n8k16.bf16.
// K-chunk 32, blocks of 64 rows/cols.
//
// A-image block (bm=row>>6, c=col>>5): 2048 u32 = [hi plane 1024][lo plane 1024]
//   ui = ((mt*2+ks)*32 + lane)*4 + comp
//   mt=(row>>4)&3, ks=(col>>4)&1, lane=((row&7)<<2)|((col>>1)&3),
//   comp=((row>>3)&1) | (((col>>3)&1)<<1);  u32 = bf16x2 of cols (kp, kp+1)
// B-image block (bn=n>>6, c=k>>5): 512 uint4 slots:
//   slot = (nt*2+ks)*32 + lane, nt=(n>>3)&7, lane=((n&7)<<2)|((k>>1)&3)
//   uint4 = (b0hi, b1hi, b0lo, b1lo); b0 = bf16x2 (k0,k0+1), b1 = (k0+8,k0+9),
//   k0 = c*32 + ks*16 + 2*(lane&3).
// s additionally kept as exact fp32 plane: per block 2048 floats, idx ui*2+(col&1).
// ---------------------------------------------------------------------------
__device__ __align__(16) u32   g_s_bf [B_I * N_N];   // s bf16 planes (NCH=64)
__device__ __align__(16) float g_s_f32[B_I * N_N];   // s exact fp32
__device__ __align__(16) u32   g_r_bf [B_I * M_M];   // r bf16 planes (NCH=16)
__device__ __align__(16) float g_bimg [B_I * M_M];   // b fp32 (r-image indexing)
__device__ __align__(16) u32   g_B1[M_M * N_N];      // gemm1 B (n=512,  k=2048)
__device__ __align__(16) u32   g_B2[N_N * M_M];      // gemm2 B (n=2048, k=512)
__device__ __align__(16) u32   g_B3[N_N * N_N];      // final B (n=2048, k=2048)

// ---------------------------------------------------------------------------
__device__ __forceinline__ uint32_t smem_u32(const void* p) {
    uint32_t a;
    asm("{ .reg .u64 t; cvta.to.shared.u64 t, %1; cvt.u32.u64 %0, t; }"
        : "=r"(a) : "l"(p));
    return a;
}
__device__ __forceinline__ float bfhi(float v) {
    return __bfloat162float(__float2bfloat16_rn(v));
}
__device__ __forceinline__ u32 packbf(float a, float b) {
    __nv_bfloat162 t = __floats2bfloat162_rn(a, b);
    return *reinterpret_cast<u32*>(&t);
}
__device__ __forceinline__ void cp16(uint32_t saddr, const void* g) {
    asm volatile("cp.async.cg.shared.global [%0], [%1], 16;"
                 :: "r"(saddr), "l"(g) : "memory");
}
#define CP_COMMIT() asm volatile("cp.async.commit_group;" ::: "memory")
#define CP_WAIT2()  asm volatile("cp.async.wait_group 2;" ::: "memory")
#define CP_WAIT1()  asm volatile("cp.async.wait_group 1;" ::: "memory")
#define CP_WAIT0()  asm volatile("cp.async.wait_group 0;" ::: "memory")

__device__ __forceinline__ uint4 lds128(uint32_t a) {
    uint4 v;
    asm volatile("ld.shared.v4.b32 {%0,%1,%2,%3}, [%4];"
                 : "=r"(v.x), "=r"(v.y), "=r"(v.z), "=r"(v.w) : "r"(a));
    return v;
}
__device__ __forceinline__ void mma16(float* c, const uint4 a,
                                      u32 b0, u32 b1) {
    asm volatile("mma.sync.aligned.m16n8k16.row.col.f32.bf16.bf16.f32 "
                 "{%0,%1,%2,%3}, {%4,%5,%6,%7}, {%8,%9}, {%0,%1,%2,%3};"
                 : "+f"(c[0]), "+f"(c[1]), "+f"(c[2]), "+f"(c[3])
                 : "r"(a.x), "r"(a.y), "r"(a.z), "r"(a.w), "r"(b0), "r"(b1));
}

__device__ __forceinline__ int a_ui(int row, int col) {
    int mt = (row >> 4) & 3, ks = (col >> 4) & 1;
    int ln = ((row & 7) << 2) | ((col >> 1) & 3);
    int cp = ((row >> 3) & 1) | (((col >> 3) & 1) << 1);
    return ((mt * 2 + ks) * 32 + ln) * 4 + cp;
}

__device__ __forceinline__ int get_idx(const void* idxp, int m) {
    const long long* p64 = (const long long*)idxp;
    if ((p64[0] >> 32) == 0LL) return (int)p64[m];
    return ((const int*)idxp)[m];
}
__device__ __forceinline__ float dct_w(int k) {
    return (k == 0) ? rsqrtf((float)N_N) : sqrtf(2.0f / (float)N_N);
}
__device__ __forceinline__ float bval(int mode, const void* idxs, int n, int k) {
    int t; float w;
    if (mode == 1)      { int j = get_idx(idxs, n); t = ((2*j+1)*k) & 8191; w = dct_w(k); }
    else if (mode == 2) { int j = get_idx(idxs, k); t = ((2*j+1)*n) & 8191; w = dct_w(n); }
    else                { t = ((2*n+1)*k) & 8191;                           w = dct_w(k); }
    return w * cospif((float)t * (1.0f / 4096.0f));
}

// ---------------------------------------------------------------------------
// setup
// ---------------------------------------------------------------------------
__global__ void k_zero_s() {
    int i = blockIdx.x * blockDim.x + threadIdx.x;
    if (i < B_I * N_N / 4) {
        ((uint4*)g_s_bf)[i] = make_uint4(0, 0, 0, 0);
        ((float4*)g_s_f32)[i] = make_float4(0.f, 0.f, 0.f, 0.f);
    }
}

__global__ void k_build_b(const float* __restrict__ x, const void* idxs) {
    int id = blockIdx.x * blockDim.x + threadIdx.x;
    if (id >= B_I * M_M) return;
    int i = id >> 9, m = id & 511;
    float v = x[(size_t)i * N_N + get_idx(idxs, m)] * 100.0f;
    size_t blk = (size_t)(i >> 6) * 16 + (m >> 5);
    g_bimg[blk * 2048 + a_ui(i, m & 31) * 2 + (m & 1)] = v;
}

#define B1_SL (8  * 64 * 512)
#define B2_SL (32 * 16 * 512)
#define B3_SL (32 * 64 * 512)
__global__ void k_build_Ball(const void* idxs) {
    int id = blockIdx.x * blockDim.x + threadIdx.x;
    uint4* img; int mode, NCH, lid;
    if (id < B1_SL)              { img = (uint4*)g_B1; mode = 1; NCH = 64; lid = id; }
    else if (id < B1_SL + B2_SL) { img = (uint4*)g_B2; mode = 2; NCH = 16; lid = id - B1_SL; }
    else if (id < B1_SL + B2_SL + B3_SL)
                                 { img = (uint4*)g_B3; mode = 3; NCH = 64; lid = id - B1_SL - B2_SL; }
    else return;
    int bn  = lid / (NCH * 512);
    int rem = lid - bn * (NCH * 512);
    int c    = rem >> 9;
    int slot = rem & 511;
    int nt = slot >> 6, ks = (slot >> 5) & 1, lane = slot & 31;
    int n  = bn * 64 + nt * 8 + (lane >> 2);
    int k0 = c * 32 + ks * 16 + 2 * (lane & 3);
    float v0 = bval(mode, idxs, n, k0);
    float v1 = bval(mode, idxs, n, k0 + 1);
    float v8 = bval(mode, idxs, n, k0 + 8);
    float v9 = bval(mode, idxs, n, k0 + 9);
    float h0 = bfhi(v0), h1 = bfhi(v1), h8 = bfhi(v8), h9 = bfhi(v9);
    img[lid] = make_uint4(packbf(h0, h1), packbf(h8, h9),
                          packbf(v0 - h0, v1 - h1), packbf(v8 - h8, v9 - h9));
}

// ---------------------------------------------------------------------------
// bf16x3 GEMM: CTA 64x64, 4 warps (2x2), warp tile 32x32.  K-chunk 32.
// 4-stage cp.async pipeline (16KB/stage = A 8K + B 8K) -> ONE sync per chunk:
// prefetch(c+3) targets the buffer last read at chunk c-1, which every warp
// has finished (they all passed this chunk's sync).
// MODE 0: r = acc - b    MODE 1: s = soft(s_f32 - acc, .05)   MODE 2: out = acc*.01
// ---------------------------------------------------------------------------
#define SMEM_SZ (4 * 16384)

__device__ __forceinline__ void prefetch_chunk(
    uint32_t su, const uint4* Ag, const uint4* Bg, int c, int tid)
{
    uint32_t d = su + (c & 3) * 16384;
    const uint4* a = Ag + (size_t)c * 512;
    const uint4* b = Bg + (size_t)c * 512;
    #pragma unroll
    for (int u = 0; u < 4; u++) {
        cp16(d + (tid + u * 128) * 16,        a + tid + u * 128);
        cp16(d + 8192 + (tid + u * 128) * 16, b + tid + u * 128);
    }
}

template<int MODE, int KTOT, int JTOT>
__global__ void __launch_bounds__(128, 3) mma_gemm(
    const u32* __restrict__ Aimg, const u32* __restrict__ Bimg,
    u32* __restrict__ OutBf, float* __restrict__ OutF,
    const float* __restrict__ Baux)
{
    constexpr int NC = KTOT / 32;
    extern __shared__ char smem[];
    const uint32_t su = smem_u32(smem);
    const int tid = threadIdx.x, lane = tid & 31, w = tid >> 5;
    const int wm = w >> 1, wn = w & 1;
    const int bx = blockIdx.x, by = blockIdx.y;

    const uint4* Ag = (const uint4*)Aimg + (size_t)by * NC * 512;
    const uint4* Bg = (const uint4*)Bimg + (size_t)bx * NC * 512;

    float acc[2][4][4];
    #pragma unroll
    for (int i = 0; i < 2; i++)
        #pragma unroll
        for (int j = 0; j < 4; j++)
            #pragma unroll
            for (int e = 0; e < 4; e++) acc[i][j][e] = 0.0f;

    prefetch_chunk(su, Ag, Bg, 0, tid); CP_COMMIT();
    prefetch_chunk(su, Ag, Bg, 1, tid); CP_COMMIT();
    prefetch_chunk(su, Ag, Bg, 2, tid); CP_COMMIT();

    for (int c = 0; c < NC; c++) {
        if (c + 2 < NC)      { CP_WAIT2(); }
        else if (c + 1 < NC) { CP_WAIT1(); }
        else                 { CP_WAIT0(); }
        __syncthreads();

        if (c + 3 < NC) {
            prefetch_chunk(su, Ag, Bg, c + 3, tid);
            CP_COMMIT();
        }

        const uint32_t sA = su + (c & 3) * 16384;
        const uint32_t sB = sA + 8192;

        #pragma unroll
        for (int ks = 0; ks < 2; ks++) {
            uint4 ahi[2], alo[2], bb[4];
            #pragma unroll
            for (int mt = 0; mt < 2; mt++) {
                uint32_t ad = sA + (((wm * 2 + mt) * 2 + ks) * 32 + lane) * 16;
                ahi[mt] = lds128(ad);
                alo[mt] = lds128(ad + 4096);
            }
            #pragma unroll
            for (int nt = 0; nt < 4; nt++)
                bb[nt] = lds128(sB + (((wn * 4 + nt) * 2 + ks) * 32 + lane) * 16);
            #pragma unroll
            for (int mt = 0; mt < 2; mt++)
                #pragma unroll
                for (int nt = 0; nt < 4; nt++)
                    mma16(acc[mt][nt], ahi[mt], bb[nt].x, bb[nt].y);  // hi*hi
            #pragma unroll
            for (int mt = 0; mt < 2; mt++)
                #pragma unroll
                for (int nt = 0; nt < 4; nt++)
                    mma16(acc[mt][nt], ahi[mt], bb[nt].z, bb[nt].w);  // hi*lo
            #pragma unroll
            for (int mt = 0; mt < 2; mt++)
                #pragma unroll
                for (int nt = 0; nt < 4; nt++)
                    mma16(acc[mt][nt], alo[mt], bb[nt].x, bb[nt].y);  // lo*hi
        }
    }

    // epilogue
    #pragma unroll
    for (int mt = 0; mt < 2; mt++) {
        #pragma unroll
        for (int nt = 0; nt < 4; nt++) {
            const int row0 = by * 64 + (wm * 2 + mt) * 16 + (lane >> 2);
            const int col  = bx * 64 + (wn * 4 + nt) * 8 + 2 * (lane & 3);
            float* a = acc[mt][nt];
            #pragma unroll
            for (int h = 0; h < 2; h++) {
                const int row = row0 + h * 8;
                float v0 = a[2 * h], v1 = a[2 * h + 1];
                if (MODE == 2) {
                    *(float2*)&OutF[(size_t)row * JTOT + col] =
                        make_float2(v0 * 0.01f, v1 * 0.01f);
                } else {
                    constexpr int NCHO = (MODE == 0) ? (M_M / 32) : (N_N / 32);
                    const size_t blk = (size_t)(row >> 6) * NCHO + (col >> 5);
                    const int ui = a_ui(row, col & 31);
                    if (MODE == 0) {
                        float2 bv = *(const float2*)&Baux[blk * 2048 + ui * 2];
                        v0 -= bv.x; v1 -= bv.y;
                    } else {
                        float2 so = *(const float2*)&OutF[blk * 2048 + ui * 2];
                        float u0 = so.x - v0, u1 = so.y - v1;
                        float t0 = fabsf(u0) - 0.05f, t1 = fabsf(u1) - 0.05f;
                        v0 = (t0 > 0.0f) ? copysignf(t0, u0) : 0.0f;
                        v1 = (t1 > 0.0f) ? copysignf(t1, u1) : 0.0f;
                        *(float2*)&OutF[blk * 2048 + ui * 2] = make_float2(v0, v1);
                    }
                    float h0 = bfhi(v0), h1 = bfhi(v1);
                    OutBf[blk * 2048 + ui]        = packbf(h0, h1);
                    OutBf[blk * 2048 + 1024 + ui] = packbf(v0 - h0, v1 - h1);
                }
            }
        }
    }
}

extern "C" void kernel_launch(void* const* d_in, const int* in_sizes, int n_in,
                              void* d_out, int out_size) {
    const float* x    = (const float*)d_in[0];
    const void*  idxs = d_in[1];
    float*       out  = (float*)d_out;

    u32 *sbf, *rbf, *B1, *B2, *B3;
    float *sf32, *bimg;
    cudaGetSymbolAddress((void**)&sbf,  g_s_bf);
    cudaGetSymbolAddress((void**)&sf32, g_s_f32);
    cudaGetSymbolAddress((void**)&rbf,  g_r_bf);
    cudaGetSymbolAddress((void**)&bimg, g_bimg);
    cudaGetSymbolAddress((void**)&B1, g_B1);
    cudaGetSymbolAddress((void**)&B2, g_B2);
    cudaGetSymbolAddress((void**)&B3, g_B3);

    cudaFuncSetAttribute(mma_gemm<0, N_N, M_M>,
                         cudaFuncAttributeMaxDynamicSharedMemorySize, SMEM_SZ);
    cudaFuncSetAttribute(mma_gemm<1, M_M, N_N>,
                         cudaFuncAttributeMaxDynamicSharedMemorySize, SMEM_SZ);
    cudaFuncSetAttribute(mma_gemm<2, N_N, N_N>,
                         cudaFuncAttributeMaxDynamicSharedMemorySize, SMEM_SZ);

    k_zero_s   <<<(B_I * N_N / 4 + 255) / 256, 256>>>();
    k_build_b  <<<(B_I * M_M + 255) / 256, 256>>>(x, idxs);
    k_build_Ball<<<(B1_SL + B2_SL + B3_SL + 255) / 256, 256>>>(idxs);

    dim3 g1(M_M / 64, B_I / 64);   // (8, 48)  = 384 CTAs
    dim3 g2(N_N / 64, B_I / 64);   // (32, 48) = 1536 CTAs
    for (int it = 0; it < NITER; ++it) {
        // r = s @ A^T - b
        mma_gemm<0, N_N, M_M><<<g1, 128, SMEM_SZ>>>(sbf, B1, rbf, nullptr, bimg);
        // s = soft(s - r @ A, 0.05)
        mma_gemm<1, M_M, N_N><<<g2, 128, SMEM_SZ>>>(rbf, B2, sbf, sf32, nullptr);
    }
    // out = idct(s) / SCALE
    mma_gemm<2, N_N, N_N><<<g2, 128, SMEM_SZ>>>(sbf, B3, nullptr, out, nullptr);
}

// round 9
// speedup vs baseline: 2.0012x; 2.0012x over previous
#include <cuda_runtime.h>
#include <cstdint>

#define B_I   3072
#define N_N   2048
#define M_M   512
#define NITER 100

// bank-conflict padding: one extra float2 per 16
#define NPAD(i) ((i) + ((i) >> 4))
#define BUFSZ 2176   // NPAD(2047)=2174 < 2176

// twiddle tables (built once per launch)
__device__ float2 g_tw[2048];   // e^{-2*pi*i*q/2048}
__device__ float2 g_ph[2048];   // e^{+i*pi*k/4096}   (DCT boundary phase)

// ---------------------------------------------------------------------------
__device__ __forceinline__ float2 cadd(float2 a, float2 b) {
    return make_float2(a.x + b.x, a.y + b.y);
}
__device__ __forceinline__ float2 csub(float2 a, float2 b) {
    return make_float2(a.x - b.x, a.y - b.y);
}
__device__ __forceinline__ float2 cmulf(float2 a, float2 b) {
    return make_float2(a.x * b.x - a.y * b.y, a.x * b.y + a.y * b.x);
}
template<int DIR>
__device__ __forceinline__ float2 rotd(float2 v) {   // multiply by DIR*i
    return (DIR < 0) ? make_float2(v.y, -v.x) : make_float2(-v.y, v.x);
}

// idxs may be int64 or int32
__device__ __forceinline__ int get_idx(const void* idxp, int m) {
    const long long* p64 = (const long long*)idxp;
    if ((p64[0] >> 32) == 0LL) return (int)p64[m];
    return ((const int*)idxp)[m];
}

// ---------------------------------------------------------------------------
// DIF radix-8 butterfly: natural-order inputs -> natural-order bins in o[]
// ---------------------------------------------------------------------------
template<int DIR>
__device__ __forceinline__ void dif8(const float2 v[8], float2 o[8]) {
    const float r = 0.70710678118654752f;
    float2 s0 = cadd(v[0], v[4]), s1 = cadd(v[1], v[5]);
    float2 s2 = cadd(v[2], v[6]), s3 = cadd(v[3], v[7]);
    float2 d0 = csub(v[0], v[4]);
    float2 d1 = csub(v[1], v[5]);
    float2 d2 = csub(v[2], v[6]);
    float2 d3 = csub(v[3], v[7]);
    if (DIR < 0) {  // W8^1=(r,-r), W8^2=-i, W8^3=(-r,-r)
        d1 = make_float2(r * (d1.x + d1.y), r * (d1.y - d1.x));
        d2 = make_float2(d2.y, -d2.x);
        d3 = make_float2(r * (d3.y - d3.x), -r * (d3.x + d3.y));
    } else {        // conjugates
        d1 = make_float2(r * (d1.x - d1.y), r * (d1.y + d1.x));
        d2 = make_float2(-d2.y, d2.x);
        d3 = make_float2(-r * (d3.x + d3.y), r * (d3.x - d3.y));
    }
    // DFT4 on s -> even bins
    float2 a0 = cadd(s0, s2), b0 = csub(s0, s2);
    float2 a1 = cadd(s1, s3), b1 = rotd<DIR>(csub(s1, s3));
    o[0] = cadd(a0, a1);
    o[4] = csub(a0, a1);
    o[2] = cadd(b0, b1);
    o[6] = csub(b0, b1);
    // DFT4 on d -> odd bins
    float2 c0 = cadd(d0, d2), e0 = csub(d0, d2);
    float2 c1 = cadd(d1, d3), e1 = rotd<DIR>(csub(d1, d3));
    o[1] = cadd(c0, c1);
    o[5] = csub(c0, c1);
    o[3] = cadd(e0, e1);
    o[7] = csub(e0, e1);
}

template<int DIR>
__device__ __forceinline__ void dif4(const float2 v[4], float2 o[4]) {
    float2 a0 = cadd(v[0], v[2]), b0 = csub(v[0], v[2]);
    float2 a1 = cadd(v[1], v[3]), b1 = rotd<DIR>(csub(v[1], v[3]));
    o[0] = cadd(a0, a1);
    o[2] = csub(a0, a1);
    o[1] = cadd(b0, b1);
    o[3] = csub(b0, b1);
}

// ---------------------------------------------------------------------------
// Stockham autosort stage (Govindaraju formulation), out-of-place.
// reads  in[j + t*(N/R)], twiddles by w^{t*(j mod Ns)}, w=e^{DIR*2pi*i/(Ns*R)}
// writes out[(j/Ns)*Ns*R + (j mod Ns) + t*Ns]
// ---------------------------------------------------------------------------
template<int R, int Ns, int DIR>
__device__ __forceinline__ void fft_stage(const float2* __restrict__ in,
                                          float2* __restrict__ out, int tid) {
    constexpr int NB  = 2048 / R;
    constexpr int TWF = 2048 / (Ns * R);
    #pragma unroll
    for (int jj = 0; jj < NB / 128; jj++) {
        const int j = tid + jj * 128;
        float2 v[R];
        #pragma unroll
        for (int t = 0; t < R; t++) v[t] = in[NPAD(j + t * NB)];
        if (Ns > 1) {
            const int q0 = (j & (Ns - 1)) * TWF;
            #pragma unroll
            for (int t = 1; t < R; t++) {
                float2 w = g_tw[t * q0];    // t*q0 < 2048 for all our stages
                if (DIR > 0) w.y = -w.y;
                v[t] = cmulf(v[t], w);
            }
        }
        float2 o[R];
        if (R == 8) dif8<DIR>(v, o); else dif4<DIR>(v, o);
        const int idxD = (j / Ns) * (Ns * R) + (j & (Ns - 1));
        #pragma unroll
        for (int t = 0; t < R; t++) out[NPAD(idxD + t * Ns)] = o[t];
    }
}

// full 2048-pt FFT: A -> ... -> result back in A
template<int DIR>
__device__ __forceinline__ void fft2048(float2* A, float2* B, int tid) {
    fft_stage<8, 1,   DIR>(A, B, tid); __syncthreads();
    fft_stage<8, 8,   DIR>(B, A, tid); __syncthreads();
    fft_stage<8, 64,  DIR>(A, B, tid); __syncthreads();
    fft_stage<4, 512, DIR>(B, A, tid); __syncthreads();
}

// ---------------------------------------------------------------------------
__global__ void k_build_tw() {
    int q = blockIdx.x * blockDim.x + threadIdx.x;
    if (q < 2048) {
        float a = (float)q * (1.0f / 1024.0f);   // angle = -pi * (q/1024)
        g_tw[q] = make_float2(cospif(a), -sinpif(a));
        float p = (float)q * (1.0f / 4096.0f);   // angle = +pi * (q/4096)
        g_ph[q] = make_float2(cospif(p), sinpif(p));
    }
}

// ---------------------------------------------------------------------------
// Persistent per-signal ISTA solver.  One CTA = one (batch, channel) signal.
//   iterate 100x:  s = soft(s - dct_o(scatter(idct_o(s)[idxs] - b)), 0.05)
//   idct_o (DCT-III) via Makhoul: X[k]=s[k]/w_k (scaled by 1/N),
//     V[k] = e^{+i pi k/2N} (X[k] - i X[N-k]),  v = IFFT(V),
//     y[2n]=v[n].re, y[2n+1]=v[N-1-n].re
//   dct_o (DCT-II): v-permute f, V=FFT(v), X[k]=Re(e^{-i pi k/2N} V[k]),
//     g[k] = w_k X[k]
// ---------------------------------------------------------------------------
#define C_K0  0.0220970869120796f   // 1/sqrt(2048)
#define C_KS  0.015625f             // sqrt(1024)/2048 = 1/64
#define W_0   0.0220970869120796f   // sqrt(1/2048)
#define W_K   0.03125f              // sqrt(2/2048) = 1/32

__global__ void __launch_bounds__(128) solver(
    const float* __restrict__ x, const void* __restrict__ idxs,
    float* __restrict__ out)
{
    __shared__ float2 bufA[BUFSZ];
    __shared__ float2 bufB[BUFSZ];
    __shared__ float  sarr[N_N];
    __shared__ float  bm[M_M];
    __shared__ int    nmap[M_M];

    const int tid = threadIdx.x;
    const int sig = blockIdx.x;
    const float* xs = x + (size_t)sig * N_N;

    // init: measurements (scaled) + v-permutation targets, s = 0
    for (int m = tid; m < M_M; m += 128) {
        int j = get_idx(idxs, m);
        bm[m] = xs[j] * 100.0f;
        nmap[m] = (j & 1) ? (2047 - ((j - 1) >> 1)) : (j >> 1);
    }
    for (int k = tid; k < N_N; k += 128) sarr[k] = 0.0f;
    __syncthreads();

    for (int it = 0; it < NITER; it++) {
        // ---- idct pre-step: build V (with 1/N folded) into bufA ----
        for (int k = tid; k < N_N; k += 128) {
            float2 V;
            if (k == 0) {
                V = make_float2(sarr[0] * C_K0, 0.0f);
            } else {
                float Xk = sarr[k] * C_KS;
                float Xm = sarr[N_N - k] * C_KS;
                float2 ph = g_ph[k];            // e^{+i pi k/4096}
                V = make_float2(ph.x * Xk + ph.y * Xm,
                                ph.y * Xk - ph.x * Xm);
            }
            bufA[NPAD(k)] = V;
        }
        __syncthreads();
        fft2048<1>(bufA, bufB, tid);            // IFFT -> v in bufA

        // ---- residual gather, zero, scatter ----
        float rloc[4];
        #pragma unroll
        for (int u = 0; u < 4; u++) {
            int m = tid + u * 128;
            rloc[u] = bufA[NPAD(nmap[m])].x - bm[m];
        }
        __syncthreads();
        for (int i = tid; i < BUFSZ; i += 128) bufA[i] = make_float2(0.f, 0.f);
        __syncthreads();
        #pragma unroll
        for (int u = 0; u < 4; u++) {
            int m = tid + u * 128;
            bufA[NPAD(nmap[m])] = make_float2(rloc[u], 0.0f);
        }
        __syncthreads();

        fft2048<-1>(bufA, bufB, tid);           // forward FFT -> V' in bufA

        // ---- dct post-step + ISTA update ----
        for (int k = tid; k < N_N; k += 128) {
            float2 V = bufA[NPAD(k)];
            float2 ph = g_ph[k];                 // conj gives e^{-i pi k/4096}
            float X = ph.x * V.x + ph.y * V.y;   // Re(conj(ph) * V)
            float g = ((k == 0) ? W_0 : W_K) * X;
            float u = sarr[k] - g;
            float t = fabsf(u) - 0.05f;
            sarr[k] = (t > 0.0f) ? copysignf(t, u) : 0.0f;
        }
        __syncthreads();
    }

    // ---- final: out = idct_o(s) / 100 ----
    for (int k = tid; k < N_N; k += 128) {
        float2 V;
        if (k == 0) {
            V = make_float2(sarr[0] * C_K0, 0.0f);
        } else {
            float Xk = sarr[k] * C_KS;
            float Xm = sarr[N_N - k] * C_KS;
            float2 ph = g_ph[k];
            V = make_float2(ph.x * Xk + ph.y * Xm, ph.y * Xk - ph.x * Xm);
        }
        bufA[NPAD(k)] = V;
    }
    __syncthreads();
    fft2048<1>(bufA, bufB, tid);

    float* os = out + (size_t)sig * N_N;
    for (int n = tid; n < N_N / 2; n += 128) {
        os[2 * n]     = bufA[NPAD(n)].x * 0.01f;
        os[2 * n + 1] = bufA[NPAD(2047 - n)].x * 0.01f;
    }
}

extern "C" void kernel_launch(void* const* d_in, const int* in_sizes, int n_in,
                              void* d_out, int out_size) {
    const float* x    = (const float*)d_in[0];
    const void*  idxs = d_in[1];
    float*       out  = (float*)d_out;

    k_build_tw<<<(2048 + 255) / 256, 256>>>();
    solver<<<B_I, 128>>>(x, idxs, out);
}

// round 10
// speedup vs baseline: 2.7531x; 1.3757x over previous
#include <cuda_runtime.h>
#include <cstdint>

#define B_I   3072
#define N_N   2048
#define H_H   1024
#define M_M   512
#define NITER 100

// bank-conflict padding: one extra float2 per 16
#define NPAD(i) ((i) + ((i) >> 4))
#define BUFSZ 1088   // NPAD(1023)=1086

// twiddle tables
__device__ float2 g_tw[2048];   // e^{-2*pi*i*q/2048}
__device__ float2 g_ph[2048];   // e^{+i*pi*k/4096}

// ---------------------------------------------------------------------------
__device__ __forceinline__ float2 cadd(float2 a, float2 b) {
    return make_float2(a.x + b.x, a.y + b.y);
}
__device__ __forceinline__ float2 csub(float2 a, float2 b) {
    return make_float2(a.x - b.x, a.y - b.y);
}
__device__ __forceinline__ float2 cmulf(float2 a, float2 b) {
    return make_float2(a.x * b.x - a.y * b.y, a.x * b.y + a.y * b.x);
}
template<int DIR>
__device__ __forceinline__ float2 rotd(float2 v) {   // multiply by DIR*i
    return (DIR < 0) ? make_float2(v.y, -v.x) : make_float2(-v.y, v.x);
}

__device__ __forceinline__ int get_idx(const void* idxp, int m) {
    const long long* p64 = (const long long*)idxp;
    if ((p64[0] >> 32) == 0LL) return (int)p64[m];
    return ((const int*)idxp)[m];
}

// ---------------------------------------------------------------------------
template<int DIR>
__device__ __forceinline__ void dif8(const float2 v[8], float2 o[8]) {
    const float r = 0.70710678118654752f;
    float2 s0 = cadd(v[0], v[4]), s1 = cadd(v[1], v[5]);
    float2 s2 = cadd(v[2], v[6]), s3 = cadd(v[3], v[7]);
    float2 d0 = csub(v[0], v[4]);
    float2 d1 = csub(v[1], v[5]);
    float2 d2 = csub(v[2], v[6]);
    float2 d3 = csub(v[3], v[7]);
    if (DIR < 0) {
        d1 = make_float2(r * (d1.x + d1.y), r * (d1.y - d1.x));
        d2 = make_float2(d2.y, -d2.x);
        d3 = make_float2(r * (d3.y - d3.x), -r * (d3.x + d3.y));
    } else {
        d1 = make_float2(r * (d1.x - d1.y), r * (d1.y + d1.x));
        d2 = make_float2(-d2.y, d2.x);
        d3 = make_float2(-r * (d3.x + d3.y), r * (d3.x - d3.y));
    }
    float2 a0 = cadd(s0, s2), b0 = csub(s0, s2);
    float2 a1 = cadd(s1, s3), b1 = rotd<DIR>(csub(s1, s3));
    o[0] = cadd(a0, a1);
    o[4] = csub(a0, a1);
    o[2] = cadd(b0, b1);
    o[6] = csub(b0, b1);
    float2 c0 = cadd(d0, d2), e0 = csub(d0, d2);
    float2 c1 = cadd(d1, d3), e1 = rotd<DIR>(csub(d1, d3));
    o[1] = cadd(c0, c1);
    o[5] = csub(c0, c1);
    o[3] = cadd(e0, e1);
    o[7] = csub(e0, e1);
}

template<int DIR>
__device__ __forceinline__ void dif4(const float2 v[4], float2 o[4]) {
    float2 a0 = cadd(v[0], v[2]), b0 = csub(v[0], v[2]);
    float2 a1 = cadd(v[1], v[3]), b1 = rotd<DIR>(csub(v[1], v[3]));
    o[0] = cadd(a0, a1);
    o[2] = csub(a0, a1);
    o[1] = cadd(b0, b1);
    o[3] = csub(b0, b1);
}

// ---------------------------------------------------------------------------
// Stockham autosort stage, 1024-pt, out-of-place.  Twiddle indexed in the
// 2048-entry table: w^p = g_tw[p * 2048/(Ns*R)].
// ---------------------------------------------------------------------------
template<int R, int Ns, int DIR>
__device__ __forceinline__ void fft_stage(const float2* __restrict__ in,
                                          float2* __restrict__ out, int tid) {
    constexpr int NB  = H_H / R;
    constexpr int TWF = 2048 / (Ns * R);
    #pragma unroll
    for (int jj = 0; jj < NB / 128; jj++) {
        const int j = tid + jj * 128;
        float2 v[R];
        #pragma unroll
        for (int t = 0; t < R; t++) v[t] = in[NPAD(j + t * NB)];
        if (Ns > 1) {
            const int q0 = (j & (Ns - 1)) * TWF;
            #pragma unroll
            for (int t = 1; t < R; t++) {
                float2 w = g_tw[t * q0];
                if (DIR > 0) w.y = -w.y;
                v[t] = cmulf(v[t], w);
            }
        }
        float2 o[R];
        if (R == 8) dif8<DIR>(v, o); else dif4<DIR>(v, o);
        const int idxD = (j / Ns) * (Ns * R) + (j & (Ns - 1));
        #pragma unroll
        for (int t = 0; t < R; t++) out[NPAD(idxD + t * Ns)] = o[t];
    }
}

// 1024-pt FFT: X -> ... -> result back in X (4 stages, ping-pong with Y)
template<int DIR>
__device__ __forceinline__ void fft1024(float2* X, float2* Y, int tid) {
    fft_stage<8, 1,   DIR>(X, Y, tid); __syncthreads();
    fft_stage<8, 8,   DIR>(Y, X, tid); __syncthreads();
    fft_stage<4, 64,  DIR>(X, Y, tid); __syncthreads();
    fft_stage<4, 256, DIR>(Y, X, tid); __syncthreads();
}

// ---------------------------------------------------------------------------
__global__ void k_build_tw() {
    int q = blockIdx.x * blockDim.x + threadIdx.x;
    if (q < 2048) {
        float a = (float)q * (1.0f / 1024.0f);
        g_tw[q] = make_float2(cospif(a), -sinpif(a));
        float p = (float)q * (1.0f / 4096.0f);
        g_ph[q] = make_float2(cospif(p), sinpif(p));
    }
}

// ---------------------------------------------------------------------------
// Per-signal ISTA solver with real-packed (N/2-point) FFTs.
//   idct: V[k]=ph[k](X[k]-iX[N-k]) (scales folded), pack
//     Z[q] = (V[q]+V[q+H]) + i*conj(tw[q])*(V[q]-V[q+H]),  z=IFFT_H(Z),
//     z[n] = v[2n] + i v[2n+1];  y[2n]=v[n], y[2n+1]=v[N-1-n]
//   dct:  Z=FFT_H(z), V'[q]=0.5(Z[q]+Z~[H-q]) - (i/2) tw[q] (Z[q]-Z~[H-q]),
//     X[k]=Re(conj(ph[k]) V'[k]), V'[N-q]=conj(V'[q])
// ---------------------------------------------------------------------------
#define C_K0  0.0220970869120796f   // 1/sqrt(2048)
#define C_KS  0.015625f             // 1/64
#define W_0   0.0220970869120796f
#define W_K   0.03125f
#define SQRT2 1.41421356237309505f

// build Z (packed idct spectrum) from sarr into Zb
__device__ __forceinline__ void build_Z(const float* __restrict__ sarr,
                                        float2* __restrict__ Zb, int tid) {
    for (int q = tid; q < H_H; q += 128) {
        float2 Vq, Vh;
        if (q == 0) {
            Vq = make_float2(sarr[0] * C_K0, 0.0f);
            Vh = make_float2(SQRT2 * sarr[H_H] * C_KS, 0.0f);
        } else {
            float Xq  = sarr[q] * C_KS;
            float Xnq = sarr[N_N - q] * C_KS;
            float2 p  = g_ph[q];
            Vq = make_float2(p.x * Xq + p.y * Xnq, p.y * Xq - p.x * Xnq);
            float Xh  = sarr[q + H_H] * C_KS;
            float Xhq = sarr[H_H - q] * C_KS;
            float2 p2 = g_ph[q + H_H];
            Vh = make_float2(p2.x * Xh + p2.y * Xhq, p2.y * Xh - p2.x * Xhq);
        }
        float2 sum = cadd(Vq, Vh);
        float2 dif = csub(Vq, Vh);
        float2 tw  = g_tw[q];                 // e^{-2pi i q/2048}
        float2 e   = make_float2(tw.x * dif.x + tw.y * dif.y,   // conj(tw)*dif
                                 tw.x * dif.y - tw.y * dif.x);
        Zb[NPAD(q)] = make_float2(sum.x - e.y, sum.y + e.x);    // sum + i*e
    }
}

__global__ void __launch_bounds__(128) solver(
    const float* __restrict__ x, const void* __restrict__ idxs,
    float* __restrict__ out)
{
    __shared__ float2 bufA[BUFSZ];
    __shared__ float2 bufB[BUFSZ];
    __shared__ float  sarr[N_N];
    __shared__ float  bm[M_M];
    __shared__ int    nmap[M_M];

    const int tid = threadIdx.x;
    const int sig = blockIdx.x;
    const float* xs = x + (size_t)sig * N_N;

    for (int m = tid; m < M_M; m += 128) {
        int j = get_idx(idxs, m);
        bm[m] = xs[j] * 100.0f;
        nmap[m] = (j & 1) ? (2047 - ((j - 1) >> 1)) : (j >> 1);
    }
    for (int k = tid; k < N_N; k += 128) sarr[k] = 0.0f;
    __syncthreads();

    for (int it = 0; it < NITER; it++) {
        // ---- idct: Z in bufA, IFFT_H -> z in bufA ----
        build_Z(sarr, bufA, tid);
        __syncthreads();
        fft1024<1>(bufA, bufB, tid);

        // ---- gather residual from z (bufA); zero bufB concurrently ----
        float rloc[4];
        #pragma unroll
        for (int u = 0; u < 4; u++) {
            int p = nmap[tid + u * 128];
            float2 zv = bufA[NPAD(p >> 1)];
            rloc[u] = ((p & 1) ? zv.y : zv.x) - bm[tid + u * 128];
        }
        for (int i = tid; i < BUFSZ; i += 128) bufB[i] = make_float2(0.f, 0.f);
        __syncthreads();
        // ---- scatter packed residual into bufB ----
        #pragma unroll
        for (int u = 0; u < 4; u++) {
            int p = nmap[tid + u * 128];
            ((float*)bufB)[2 * NPAD(p >> 1) + (p & 1)] = rloc[u];
        }
        __syncthreads();

        // ---- forward FFT_H of packed residual: bufB -> bufB ----
        fft1024<-1>(bufB, bufA, tid);

        // ---- unpack + dct post + ISTA update (pairs k=q, N-q) ----
        for (int q = tid; q < H_H; q += 128) {
            if (q == 0) {
                float2 Z0 = bufB[NPAD(0)];
                float v0 = Z0.x + Z0.y;          // V'[0]
                float vh = Z0.x - Z0.y;          // V'[H]
                float g0 = W_0 * v0;
                float gh = W_K * (g_ph[H_H].x * vh);
                float u0 = sarr[0] - g0;
                float t0 = fabsf(u0) - 0.05f;
                sarr[0] = (t0 > 0.0f) ? copysignf(t0, u0) : 0.0f;
                float uh = sarr[H_H] - gh;
                float th = fabsf(uh) - 0.05f;
                sarr[H_H] = (th > 0.0f) ? copysignf(th, uh) : 0.0f;
            } else {
                float2 Zq = bufB[NPAD(q)];
                float2 Zr = bufB[NPAD(H_H - q)];
                float2 Zm = make_float2(Zr.x, -Zr.y);          // conj
                float2 Es = make_float2(0.5f * (Zq.x + Zm.x),
                                        0.5f * (Zq.y + Zm.y));
                float2 Os = csub(Zq, Zm);
                float2 t  = cmulf(g_tw[q], Os);
                float2 V  = make_float2(Es.x + 0.5f * t.y,
                                        Es.y - 0.5f * t.x);    // Es - (i/2)t
                float2 p1 = g_ph[q];
                float Xq  = p1.x * V.x + p1.y * V.y;
                float2 p2 = g_ph[N_N - q];
                float Xnq = p2.x * V.x - p2.y * V.y;
                float uq = sarr[q] - W_K * Xq;
                float tq = fabsf(uq) - 0.05f;
                sarr[q] = (tq > 0.0f) ? copysignf(tq, uq) : 0.0f;
                float un = sarr[N_N - q] - W_K * Xnq;
                float tn = fabsf(un) - 0.05f;
                sarr[N_N - q] = (tn > 0.0f) ? copysignf(tn, un) : 0.0f;
            }
        }
        __syncthreads();
    }

    // ---- final: y = idct(s) / 100 ----
    build_Z(sarr, bufA, tid);
    __syncthreads();
    fft1024<1>(bufA, bufB, tid);

    float* os = out + (size_t)sig * N_N;
    for (int j = tid; j < N_N; j += 128) {
        float2 zv = bufA[NPAD(j >> 1)];
        float v = (j & 1) ? zv.y : zv.x;
        int o = (j < H_H) ? (2 * j) : (2 * (2047 - j) + 1);
        os[o] = v * 0.01f;
    }
}

extern "C" void kernel_launch(void* const* d_in, const int* in_sizes, int n_in,
                              void* d_out, int out_size) {
    const float* x    = (const float*)d_in[0];
    const void*  idxs = d_in[1];
    float*       out  = (float*)d_out;

    k_build_tw<<<(2048 + 255) / 256, 256>>>();
    solver<<<B_I, 128>>>(x, idxs, out);
}